// round 5
// baseline (speedup 1.0000x reference)
#include <cuda_runtime.h>
#include <math.h>

// Problem constants
#define BB 4
#define NN 2048
#define DIM 512
#define HEADS 8
#define DH 64
#define HIDDEN 512          // HEADS*DH
#define THC 1536            // 3*HIDDEN

// ---------------- scratch (device globals: allocation-free rule) ----------
__device__ float g_qkv[(size_t)BB * NN * THC];        // 48 MB
__device__ float g_q  [(size_t)BB * HEADS * NN * DH]; // 16 MB
__device__ float g_k  [(size_t)BB * HEADS * NN * DH]; // 16 MB
__device__ float g_v  [(size_t)BB * HEADS * NN * DH]; // 16 MB
__device__ float g_mid[(size_t)BB * NN * HIDDEN];     // 16 MB

// inv_freq[i] = 10000^(-2i/64) = 10^(-i/8), correctly-rounded fp32
__constant__ float c_invfreq[32] = {
    1.0f,
    0.74989420933245582f, 0.56234132519034907f, 0.42169650342858220f,
    0.31622776601683794f, 0.23713737056616552f, 0.17782794100389228f,
    0.13335214321633240f, 0.1f,
    0.074989420933245582f, 0.056234132519034907f, 0.042169650342858220f,
    0.031622776601683794f, 0.023713737056616552f, 0.017782794100389228f,
    0.013335214321633240f, 0.01f,
    0.0074989420933245582f, 0.0056234132519034907f, 0.0042169650342858220f,
    0.0031622776601683794f, 0.0023713737056616552f, 0.0017782794100389228f,
    0.0013335214321633240f, 0.001f,
    0.00074989420933245582f, 0.00056234132519034907f, 0.00042169650342858220f,
    0.00031622776601683794f, 0.00023713737056616552f, 0.00017782794100389228f,
    0.00013335214321633240f
};

// =====================================================================
// SGEMM: C[M,Nc] = A[M,K] @ B[K,Nc], all row-major fp32.
// 64x64 tile, BK=16, 256 threads, 4x4 register tile per thread.
// A tile stored k-major (transposed) with stride 68 for float4 loads.
// =====================================================================
__global__ __launch_bounds__(256)
void sgemm64(const float* __restrict__ A, const float* __restrict__ Bm,
             float* __restrict__ C, int M, int Nc, int K)
{
    __shared__ float Ast[16 * 68];   // [k][m], stride 68
    __shared__ float Bs [16 * 64];   // [k][n]

    const int tid = threadIdx.x;
    const int tx  = tid & 15;
    const int ty  = tid >> 4;
    const int m0  = blockIdx.y * 64;
    const int n0  = blockIdx.x * 64;

    float acc[4][4];
#pragma unroll
    for (int i = 0; i < 4; ++i)
#pragma unroll
        for (int j = 0; j < 4; ++j) acc[i][j] = 0.f;

    const int ar  = tid >> 2;          // 0..63 (row within A tile)
    const int ak4 = (tid & 3) * 4;     // 0,4,8,12
    const int bk  = tid >> 4;          // 0..15
    const int bc4 = (tid & 15) * 4;    // 0..60

    for (int k0 = 0; k0 < K; k0 += 16) {
        // A tile -> Ast transposed
        float4 av = *(const float4*)&A[(size_t)(m0 + ar) * K + k0 + ak4];
        Ast[(ak4 + 0) * 68 + ar] = av.x;
        Ast[(ak4 + 1) * 68 + ar] = av.y;
        Ast[(ak4 + 2) * 68 + ar] = av.z;
        Ast[(ak4 + 3) * 68 + ar] = av.w;
        // B tile -> Bs row-major
        *(float4*)&Bs[bk * 64 + bc4] =
            *(const float4*)&Bm[(size_t)(k0 + bk) * Nc + n0 + bc4];
        __syncthreads();

#pragma unroll
        for (int k = 0; k < 16; ++k) {
            float4 a = *(const float4*)&Ast[k * 68 + (ty << 2)];
            float4 b = *(const float4*)&Bs [k * 64 + (tx << 2)];
            acc[0][0] += a.x * b.x; acc[0][1] += a.x * b.y; acc[0][2] += a.x * b.z; acc[0][3] += a.x * b.w;
            acc[1][0] += a.y * b.x; acc[1][1] += a.y * b.y; acc[1][2] += a.y * b.z; acc[1][3] += a.y * b.w;
            acc[2][0] += a.z * b.x; acc[2][1] += a.z * b.y; acc[2][2] += a.z * b.z; acc[2][3] += a.z * b.w;
            acc[3][0] += a.w * b.x; acc[3][1] += a.w * b.y; acc[3][2] += a.w * b.z; acc[3][3] += a.w * b.w;
        }
        __syncthreads();
    }

#pragma unroll
    for (int i = 0; i < 4; ++i) {
        float4 o = make_float4(acc[i][0], acc[i][1], acc[i][2], acc[i][3]);
        *(float4*)&C[(size_t)(m0 + (ty << 2) + i) * Nc + n0 + (tx << 2)] = o;
    }
}

// =====================================================================
// QKV split + head reshape + rotary (+ q scale). One thread per
// (b,h,n,pair); pair covers dims (2i, 2i+1).
// =====================================================================
__global__ __launch_bounds__(256)
void qkv_transform()
{
    const int idx  = blockIdx.x * 256 + threadIdx.x;   // B*H*N*32 threads
    const int pair = idx & 31;
    const int n    = (idx >> 5) & (NN - 1);
    const int bh   = idx >> 16;                        // b*HEADS + h
    const int b    = bh >> 3;
    const int h    = bh & 7;

    const float* src = g_qkv + (size_t)(b * NN + n) * THC;
    const int col = h * DH + pair * 2;

    float2 qv = *(const float2*)&src[col];
    float2 kv = *(const float2*)&src[HIDDEN + col];
    float2 vv = *(const float2*)&src[2 * HIDDEN + col];

    float fr = (float)n * c_invfreq[pair];
    float sn, cs;
    sincosf(fr, &sn, &cs);

    const float scale = 0.125f;   // DH^-0.5
    float oq0 = (qv.x * cs - qv.y * sn) * scale;
    float oq1 = (qv.y * cs + qv.x * sn) * scale;
    float ok0 = kv.x * cs - kv.y * sn;
    float ok1 = kv.y * cs + kv.x * sn;

    size_t o = ((size_t)bh * NN + n) * DH + pair * 2;
    g_q[o] = oq0; g_q[o + 1] = oq1;
    g_k[o] = ok0; g_k[o + 1] = ok1;
    g_v[o] = vv.x; g_v[o + 1] = vv.y;
}

// =====================================================================
// Fused flash attention, fp32.
// grid = (N/64, HEADS, B), block = 256 threads (16x16 logical).
// Q tile 64 rows, key tiles of 32. Thread computes S 4x2, O 4x4.
// smem: Qt[d][r] s68, Kt[d][c] s36, Vs[kk][c] s68, Pst[kk][r] s68.
// Total 44032 B (static, < 48KB).
// =====================================================================
__global__ __launch_bounds__(256)
void attn_kernel(const float* __restrict__ bias)
{
    __shared__ float Qt [64 * 68];
    __shared__ float Kt [64 * 36];
    __shared__ float Vs [32 * 68];
    __shared__ float Pst[32 * 68];

    const int tid = threadIdx.x;
    const int tx  = tid & 15;
    const int ty  = tid >> 4;
    const int q0  = blockIdx.x * 64;
    const int h   = blockIdx.y;
    const int b   = blockIdx.z;
    const size_t base = ((size_t)(b * HEADS + h)) * NN * DH;
    const float* biash = bias + (size_t)h * NN * NN;

    // load Q tile transposed: Qt[d][r]
#pragma unroll
    for (int i = tid; i < 64 * 16; i += 256) {
        int r  = i >> 4;
        int d4 = (i & 15) * 4;
        float4 t = *(const float4*)&g_q[base + (size_t)(q0 + r) * DH + d4];
        Qt[(d4 + 0) * 68 + r] = t.x;
        Qt[(d4 + 1) * 68 + r] = t.y;
        Qt[(d4 + 2) * 68 + r] = t.z;
        Qt[(d4 + 3) * 68 + r] = t.w;
    }

    float m_i[4], l_i[4], O[4][4];
#pragma unroll
    for (int i = 0; i < 4; ++i) {
        m_i[i] = -INFINITY; l_i[i] = 0.f;
#pragma unroll
        for (int j = 0; j < 4; ++j) O[i][j] = 0.f;
    }

    for (int j0 = 0; j0 < NN; j0 += 32) {
        __syncthreads();   // prior PV-phase reads of Kt/Vs/Pst complete

        // K tile transposed: Kt[d][c], c in 0..31
#pragma unroll
        for (int i = tid; i < 32 * 16; i += 256) {
            int c  = i >> 4;
            int d4 = (i & 15) * 4;
            float4 t = *(const float4*)&g_k[base + (size_t)(j0 + c) * DH + d4];
            Kt[(d4 + 0) * 36 + c] = t.x;
            Kt[(d4 + 1) * 36 + c] = t.y;
            Kt[(d4 + 2) * 36 + c] = t.z;
            Kt[(d4 + 3) * 36 + c] = t.w;
        }
        // V tile row-major: Vs[kk][c]
#pragma unroll
        for (int i = tid; i < 32 * 16; i += 256) {
            int r  = i >> 4;
            int d4 = (i & 15) * 4;
            *(float4*)&Vs[r * 68 + d4] =
                *(const float4*)&g_v[base + (size_t)(j0 + r) * DH + d4];
        }
        __syncthreads();

        // ---- S = Q K^T + bias  (4 rows x 2 cols per thread) ----
        float S[4][2];
#pragma unroll
        for (int i = 0; i < 4; ++i) {
            float2 bb = *(const float2*)
                &biash[(size_t)(q0 + (ty << 2) + i) * NN + j0 + (tx << 1)];
            S[i][0] = bb.x; S[i][1] = bb.y;
        }
#pragma unroll 8
        for (int d = 0; d < 64; ++d) {
            float4 a = *(const float4*)&Qt[d * 68 + (ty << 2)];
            float2 bq = *(const float2*)&Kt[d * 36 + (tx << 1)];
            S[0][0] += a.x * bq.x; S[0][1] += a.x * bq.y;
            S[1][0] += a.y * bq.x; S[1][1] += a.y * bq.y;
            S[2][0] += a.z * bq.x; S[2][1] += a.z * bq.y;
            S[3][0] += a.w * bq.x; S[3][1] += a.w * bq.y;
        }

        // ---- online softmax (row reductions across tx via width-16 shfl) --
#pragma unroll
        for (int i = 0; i < 4; ++i) {
            float tm = fmaxf(S[i][0], S[i][1]);
#pragma unroll
            for (int off = 8; off >= 1; off >>= 1)
                tm = fmaxf(tm, __shfl_xor_sync(0xffffffffu, tm, off, 16));
            float mn = fmaxf(m_i[i], tm);
            float al = __expf(m_i[i] - mn);
            m_i[i] = mn;
            float p0 = __expf(S[i][0] - mn);
            float p1 = __expf(S[i][1] - mn);
            float ts = p0 + p1;
#pragma unroll
            for (int off = 8; off >= 1; off >>= 1)
                ts += __shfl_xor_sync(0xffffffffu, ts, off, 16);
            l_i[i] = l_i[i] * al + ts;
#pragma unroll
            for (int j = 0; j < 4; ++j) O[i][j] *= al;
            // store P transposed: Pst[kk][r]
            Pst[((tx << 1) + 0) * 68 + (ty << 2) + i] = p0;
            Pst[((tx << 1) + 1) * 68 + (ty << 2) + i] = p1;
        }
        __syncthreads();

        // ---- O += P @ V ----
#pragma unroll 8
        for (int kk = 0; kk < 32; ++kk) {
            float4 a = *(const float4*)&Pst[kk * 68 + (ty << 2)];
            float4 v = *(const float4*)&Vs [kk * 68 + (tx << 2)];
            O[0][0] += a.x * v.x; O[0][1] += a.x * v.y; O[0][2] += a.x * v.z; O[0][3] += a.x * v.w;
            O[1][0] += a.y * v.x; O[1][1] += a.y * v.y; O[1][2] += a.y * v.z; O[1][3] += a.y * v.w;
            O[2][0] += a.z * v.x; O[2][1] += a.z * v.y; O[2][2] += a.z * v.z; O[2][3] += a.z * v.w;
            O[3][0] += a.w * v.x; O[3][1] += a.w * v.y; O[3][2] += a.w * v.z; O[3][3] += a.w * v.w;
        }
    }

    // ---- finalize: /l and write to [b, n, h*64 + c] for the output GEMM ----
#pragma unroll
    for (int i = 0; i < 4; ++i) {
        float inv = 1.f / l_i[i];
        float4 o = make_float4(O[i][0] * inv, O[i][1] * inv,
                               O[i][2] * inv, O[i][3] * inv);
        *(float4*)&g_mid[(size_t)(b * NN + q0 + (ty << 2) + i) * HIDDEN
                         + h * DH + (tx << 2)] = o;
    }
}

// =====================================================================
extern "C" void kernel_launch(void* const* d_in, const int* in_sizes, int n_in,
                              void* d_out, int out_size)
{
    const float *x = nullptr, *bias = nullptr, *wqkv = nullptr, *wout = nullptr;
    for (int i = 0; i < n_in; ++i) {
        switch (in_sizes[i]) {
            case 4194304:  x    = (const float*)d_in[i]; break;  // x [4,2048,512]
            case 33554432: bias = (const float*)d_in[i]; break;  // pos_bias [8,2048,2048]
            case 786432:   wqkv = (const float*)d_in[i]; break;  // W_qkv [512,1536]
            case 262144:   wout = (const float*)d_in[i]; break;  // W_out [512,512]
        }
    }

    void *p_qkv = nullptr, *p_mid = nullptr;
    cudaGetSymbolAddress(&p_qkv, g_qkv);
    cudaGetSymbolAddress(&p_mid, g_mid);

    // 1) qkv = x @ W_qkv
    sgemm64<<<dim3(THC / 64, (BB * NN) / 64), 256>>>(
        x, wqkv, (float*)p_qkv, BB * NN, THC, DIM);

    // 2) split + rotary + scale
    qkv_transform<<<(BB * HEADS * NN * 32) / 256, 256>>>();

    // 3) fused flash attention (+pos_bias, softmax)
    attn_kernel<<<dim3(NN / 64, HEADS, BB), 256>>>(bias);

    // 4) out = mid @ W_out
    sgemm64<<<dim3(DIM / 64, (BB * NN) / 64), 256>>>(
        (const float*)p_mid, wout, (float*)d_out, BB * NN, DIM, HIDDEN);
}

// round 6
// speedup vs baseline: 1.8940x; 1.8940x over previous
#include <cuda_runtime.h>
#include <math.h>

// Problem constants
#define BB 4
#define NN 2048
#define DIM 512
#define HEADS 8
#define DH 64
#define HIDDEN 512          // HEADS*DH
#define THC 1536            // 3*HIDDEN

// ---------------- scratch (device globals: allocation-free rule) ----------
__device__ float g_qkv[(size_t)BB * NN * THC];        // 48 MB
__device__ float g_q  [(size_t)BB * HEADS * NN * DH]; // 16 MB
__device__ float g_k  [(size_t)BB * HEADS * NN * DH]; // 16 MB
__device__ float g_v  [(size_t)BB * HEADS * NN * DH]; // 16 MB
__device__ float g_mid[(size_t)BB * NN * HIDDEN];     // 16 MB

// inv_freq[i] = 10000^(-2i/64) = 10^(-i/8), correctly-rounded fp32
__constant__ float c_invfreq[32] = {
    1.0f,
    0.74989420933245582f, 0.56234132519034907f, 0.42169650342858220f,
    0.31622776601683794f, 0.23713737056616552f, 0.17782794100389228f,
    0.13335214321633240f, 0.1f,
    0.074989420933245582f, 0.056234132519034907f, 0.042169650342858220f,
    0.031622776601683794f, 0.023713737056616552f, 0.017782794100389228f,
    0.013335214321633240f, 0.01f,
    0.0074989420933245582f, 0.0056234132519034907f, 0.0042169650342858220f,
    0.0031622776601683794f, 0.0023713737056616552f, 0.0017782794100389228f,
    0.0013335214321633240f, 0.001f,
    0.00074989420933245582f, 0.00056234132519034907f, 0.00042169650342858220f,
    0.00031622776601683794f, 0.00023713737056616552f, 0.00017782794100389228f,
    0.00013335214321633240f
};

// ---------------- tf32 helpers ----------------
__device__ __forceinline__ unsigned cvt_tf32(float f) {
    unsigned r;
    asm("cvt.rna.tf32.f32 %0, %1;" : "=r"(r) : "f"(f));
    return r;
}

__device__ __forceinline__ void mma_tf32(float c[4],
                                         unsigned a0, unsigned a1,
                                         unsigned a2, unsigned a3,
                                         unsigned b0, unsigned b1) {
    asm volatile(
        "mma.sync.aligned.m16n8k8.row.col.f32.tf32.tf32.f32 "
        "{%0,%1,%2,%3}, {%4,%5,%6,%7}, {%8,%9}, {%0,%1,%2,%3};\n"
        : "+f"(c[0]), "+f"(c[1]), "+f"(c[2]), "+f"(c[3])
        : "r"(a0), "r"(a1), "r"(a2), "r"(a3), "r"(b0), "r"(b1));
}

// =====================================================================
// SGEMM: C[M,Nc] = A[M,K] @ B[K,Nc], all row-major fp32.
// 64x64 tile, BK=16, 256 threads, 4x4 register tile per thread.
// =====================================================================
__global__ __launch_bounds__(256)
void sgemm64(const float* __restrict__ A, const float* __restrict__ Bm,
             float* __restrict__ C, int M, int Nc, int K)
{
    __shared__ float Ast[16 * 68];   // [k][m], stride 68
    __shared__ float Bs [16 * 64];   // [k][n]

    const int tid = threadIdx.x;
    const int tx  = tid & 15;
    const int ty  = tid >> 4;
    const int m0  = blockIdx.y * 64;
    const int n0  = blockIdx.x * 64;

    float acc[4][4];
#pragma unroll
    for (int i = 0; i < 4; ++i)
#pragma unroll
        for (int j = 0; j < 4; ++j) acc[i][j] = 0.f;

    const int ar  = tid >> 2;
    const int ak4 = (tid & 3) * 4;
    const int bk  = tid >> 4;
    const int bc4 = (tid & 15) * 4;

    for (int k0 = 0; k0 < K; k0 += 16) {
        float4 av = *(const float4*)&A[(size_t)(m0 + ar) * K + k0 + ak4];
        Ast[(ak4 + 0) * 68 + ar] = av.x;
        Ast[(ak4 + 1) * 68 + ar] = av.y;
        Ast[(ak4 + 2) * 68 + ar] = av.z;
        Ast[(ak4 + 3) * 68 + ar] = av.w;
        *(float4*)&Bs[bk * 64 + bc4] =
            *(const float4*)&Bm[(size_t)(k0 + bk) * Nc + n0 + bc4];
        __syncthreads();

#pragma unroll
        for (int k = 0; k < 16; ++k) {
            float4 a = *(const float4*)&Ast[k * 68 + (ty << 2)];
            float4 b = *(const float4*)&Bs [k * 64 + (tx << 2)];
            acc[0][0] += a.x * b.x; acc[0][1] += a.x * b.y; acc[0][2] += a.x * b.z; acc[0][3] += a.x * b.w;
            acc[1][0] += a.y * b.x; acc[1][1] += a.y * b.y; acc[1][2] += a.y * b.z; acc[1][3] += a.y * b.w;
            acc[2][0] += a.z * b.x; acc[2][1] += a.z * b.y; acc[2][2] += a.z * b.z; acc[2][3] += a.z * b.w;
            acc[3][0] += a.w * b.x; acc[3][1] += a.w * b.y; acc[3][2] += a.w * b.z; acc[3][3] += a.w * b.w;
        }
        __syncthreads();
    }

#pragma unroll
    for (int i = 0; i < 4; ++i) {
        float4 o = make_float4(acc[i][0], acc[i][1], acc[i][2], acc[i][3]);
        *(float4*)&C[(size_t)(m0 + (ty << 2) + i) * Nc + n0 + (tx << 2)] = o;
    }
}

// =====================================================================
// QKV split + head reshape + rotary (+ q scale).
// =====================================================================
__global__ __launch_bounds__(256)
void qkv_transform()
{
    const int idx  = blockIdx.x * 256 + threadIdx.x;
    const int pair = idx & 31;
    const int n    = (idx >> 5) & (NN - 1);
    const int bh   = idx >> 16;
    const int b    = bh >> 3;
    const int h    = bh & 7;

    const float* src = g_qkv + (size_t)(b * NN + n) * THC;
    const int col = h * DH + pair * 2;

    float2 qv = *(const float2*)&src[col];
    float2 kv = *(const float2*)&src[HIDDEN + col];
    float2 vv = *(const float2*)&src[2 * HIDDEN + col];

    float fr = (float)n * c_invfreq[pair];
    float sn, cs;
    sincosf(fr, &sn, &cs);

    const float scale = 0.125f;
    float oq0 = (qv.x * cs - qv.y * sn) * scale;
    float oq1 = (qv.y * cs + qv.x * sn) * scale;
    float ok0 = kv.x * cs - kv.y * sn;
    float ok1 = kv.y * cs + kv.x * sn;

    size_t o = ((size_t)bh * NN + n) * DH + pair * 2;
    g_q[o] = oq0; g_q[o + 1] = oq1;
    g_k[o] = ok0; g_k[o + 1] = ok1;
    g_v[o] = vv.x; g_v[o + 1] = vv.y;
}

// =====================================================================
// Fused flash attention, tf32 tensor cores.
// grid = (NN/128, HEADS, BB), block = 256 (8 warps, each owns 16 q rows).
// KV chunk = 64 keys. S = Q K^T + bias via mma.m16n8k8 (bias preloaded
// into accumulators). Online softmax in fp32. PV via mma with P
// re-fragmented through quad shuffles.
// smem: Ks 64x68 u32 (stride 68 -> conflict-free K B-frag loads),
//       Vs 64x72 u32 (stride 72 -> conflict-free V B-frag loads). 35.8 KB.
// =====================================================================
__global__ __launch_bounds__(256, 2)
void attn_tf32(const float* __restrict__ bias)
{
    __shared__ unsigned Ks[64 * 68];
    __shared__ unsigned Vs[64 * 72];

    const int tid  = threadIdx.x;
    const int lane = tid & 31;
    const int w    = tid >> 5;        // warp 0..7
    const int qg   = lane >> 2;       // 0..7 (row within fragment)
    const int q    = lane & 3;        // 0..3 (quad index)
    const int qblk = blockIdx.x * 128;
    const int h    = blockIdx.y;
    const int b    = blockIdx.z;
    const size_t base = ((size_t)(b * HEADS + h)) * NN * DH;
    const float* biasw = bias + (size_t)h * NN * NN
                              + (size_t)(qblk + w * 16) * NN;

    // ---- Q fragments, register-resident (loaded once) ----
    unsigned qa[8][4];
    {
        const float* Qp = g_q + base + (size_t)(qblk + w * 16) * DH;
#pragma unroll
        for (int kc = 0; kc < 8; ++kc) {
            qa[kc][0] = cvt_tf32(Qp[(size_t)qg      * DH + kc * 8 + q]);
            qa[kc][1] = cvt_tf32(Qp[(size_t)(qg + 8) * DH + kc * 8 + q]);
            qa[kc][2] = cvt_tf32(Qp[(size_t)qg      * DH + kc * 8 + q + 4]);
            qa[kc][3] = cvt_tf32(Qp[(size_t)(qg + 8) * DH + kc * 8 + q + 4]);
        }
    }

    float O[8][4];
#pragma unroll
    for (int n = 0; n < 8; ++n)
#pragma unroll
        for (int j = 0; j < 4; ++j) O[n][j] = 0.f;
    float m0 = -INFINITY, m1 = -INFINITY, l0 = 0.f, l1 = 0.f;

    for (int j0 = 0; j0 < NN; j0 += 64) {
        __syncthreads();   // previous chunk's Ks/Vs reads complete

        // ---- load + tf32-convert K,V chunk (64x64 each) ----
#pragma unroll
        for (int it = 0; it < 4; ++it) {
            int i  = tid + it * 256;
            int r  = i >> 4;
            int c4 = (i & 15) * 4;
            float4 kf = *(const float4*)&g_k[base + (size_t)(j0 + r) * DH + c4];
            float4 vf = *(const float4*)&g_v[base + (size_t)(j0 + r) * DH + c4];
            uint4 ku = make_uint4(cvt_tf32(kf.x), cvt_tf32(kf.y),
                                  cvt_tf32(kf.z), cvt_tf32(kf.w));
            uint4 vu = make_uint4(cvt_tf32(vf.x), cvt_tf32(vf.y),
                                  cvt_tf32(vf.z), cvt_tf32(vf.w));
            *(uint4*)&Ks[r * 68 + c4] = ku;
            *(uint4*)&Vs[r * 72 + c4] = vu;
        }
        __syncthreads();

        // ---- S = bias; S += Q K^T ----
        float S[8][4];
#pragma unroll
        for (int t = 0; t < 8; ++t) {
            float2 blo = *(const float2*)
                &biasw[(size_t)qg       * NN + j0 + t * 8 + 2 * q];
            float2 bhi = *(const float2*)
                &biasw[(size_t)(qg + 8) * NN + j0 + t * 8 + 2 * q];
            S[t][0] = blo.x; S[t][1] = blo.y;
            S[t][2] = bhi.x; S[t][3] = bhi.y;
        }
#pragma unroll
        for (int kc = 0; kc < 8; ++kc) {
#pragma unroll
            for (int t = 0; t < 8; ++t) {
                unsigned b0 = Ks[(t * 8 + qg) * 68 + kc * 8 + q];
                unsigned b1 = Ks[(t * 8 + qg) * 68 + kc * 8 + q + 4];
                mma_tf32(S[t], qa[kc][0], qa[kc][1], qa[kc][2], qa[kc][3],
                         b0, b1);
            }
        }

        // ---- online softmax (rows qg and qg+8; quad owns a row) ----
        float cm0 = -INFINITY, cm1 = -INFINITY;
#pragma unroll
        for (int t = 0; t < 8; ++t) {
            cm0 = fmaxf(cm0, fmaxf(S[t][0], S[t][1]));
            cm1 = fmaxf(cm1, fmaxf(S[t][2], S[t][3]));
        }
        cm0 = fmaxf(cm0, __shfl_xor_sync(0xffffffffu, cm0, 1));
        cm0 = fmaxf(cm0, __shfl_xor_sync(0xffffffffu, cm0, 2));
        cm1 = fmaxf(cm1, __shfl_xor_sync(0xffffffffu, cm1, 1));
        cm1 = fmaxf(cm1, __shfl_xor_sync(0xffffffffu, cm1, 2));

        float mn0 = fmaxf(m0, cm0), mn1 = fmaxf(m1, cm1);
        float al0 = __expf(m0 - mn0), al1 = __expf(m1 - mn1);
        m0 = mn0; m1 = mn1;

        float s0 = 0.f, s1 = 0.f;
#pragma unroll
        for (int t = 0; t < 8; ++t) {
            S[t][0] = __expf(S[t][0] - mn0);
            S[t][1] = __expf(S[t][1] - mn0);
            S[t][2] = __expf(S[t][2] - mn1);
            S[t][3] = __expf(S[t][3] - mn1);
            s0 += S[t][0] + S[t][1];
            s1 += S[t][2] + S[t][3];
        }
        s0 += __shfl_xor_sync(0xffffffffu, s0, 1);
        s0 += __shfl_xor_sync(0xffffffffu, s0, 2);
        s1 += __shfl_xor_sync(0xffffffffu, s1, 1);
        s1 += __shfl_xor_sync(0xffffffffu, s1, 2);
        l0 = l0 * al0 + s0;
        l1 = l1 * al1 + s1;
#pragma unroll
        for (int n = 0; n < 8; ++n) {
            O[n][0] *= al0; O[n][1] *= al0;
            O[n][2] *= al1; O[n][3] *= al1;
        }

        // ---- O += P @ V  (re-fragment P via quad shuffles) ----
        const int srcA = (lane & ~3) | (q >> 1);
        const int srcB = srcA | 2;
#pragma unroll
        for (int t = 0; t < 8; ++t) {
            unsigned p0 = cvt_tf32(S[t][0]);
            unsigned p1 = cvt_tf32(S[t][1]);
            unsigned p2 = cvt_tf32(S[t][2]);
            unsigned p3 = cvt_tf32(S[t][3]);
            unsigned u0 = __shfl_sync(0xffffffffu, p0, srcA);
            unsigned u1 = __shfl_sync(0xffffffffu, p1, srcA);
            unsigned v0 = __shfl_sync(0xffffffffu, p0, srcB);
            unsigned v1 = __shfl_sync(0xffffffffu, p1, srcB);
            unsigned w0 = __shfl_sync(0xffffffffu, p2, srcA);
            unsigned w1 = __shfl_sync(0xffffffffu, p3, srcA);
            unsigned x0 = __shfl_sync(0xffffffffu, p2, srcB);
            unsigned x1 = __shfl_sync(0xffffffffu, p3, srcB);
            unsigned a0 = (q & 1) ? u1 : u0;   // (row qg,   col q)
            unsigned a1 = (q & 1) ? w1 : w0;   // (row qg+8, col q)
            unsigned a2 = (q & 1) ? v1 : v0;   // (row qg,   col q+4)
            unsigned a3 = (q & 1) ? x1 : x0;   // (row qg+8, col q+4)
#pragma unroll
            for (int n = 0; n < 8; ++n) {
                unsigned b0 = Vs[(t * 8 + q)     * 72 + n * 8 + qg];
                unsigned b1 = Vs[(t * 8 + q + 4) * 72 + n * 8 + qg];
                mma_tf32(O[n], a0, a1, a2, a3, b0, b1);
            }
        }
    }

    // ---- finalize: /l, write to g_mid[b, n, h*64 + c] ----
    const float il0 = 1.f / l0, il1 = 1.f / l1;
    const int row0 = qblk + w * 16 + qg;
    const int row1 = row0 + 8;
#pragma unroll
    for (int n = 0; n < 8; ++n) {
        float2 olo = make_float2(O[n][0] * il0, O[n][1] * il0);
        float2 ohi = make_float2(O[n][2] * il1, O[n][3] * il1);
        *(float2*)&g_mid[(size_t)(b * NN + row0) * HIDDEN
                         + h * DH + n * 8 + 2 * q] = olo;
        *(float2*)&g_mid[(size_t)(b * NN + row1) * HIDDEN
                         + h * DH + n * 8 + 2 * q] = ohi;
    }
}

// =====================================================================
extern "C" void kernel_launch(void* const* d_in, const int* in_sizes, int n_in,
                              void* d_out, int out_size)
{
    const float *x = nullptr, *bias = nullptr, *wqkv = nullptr, *wout = nullptr;
    for (int i = 0; i < n_in; ++i) {
        switch (in_sizes[i]) {
            case 4194304:  x    = (const float*)d_in[i]; break;  // x [4,2048,512]
            case 33554432: bias = (const float*)d_in[i]; break;  // pos_bias [8,2048,2048]
            case 786432:   wqkv = (const float*)d_in[i]; break;  // W_qkv [512,1536]
            case 262144:   wout = (const float*)d_in[i]; break;  // W_out [512,512]
        }
    }

    void *p_qkv = nullptr, *p_mid = nullptr;
    cudaGetSymbolAddress(&p_qkv, g_qkv);
    cudaGetSymbolAddress(&p_mid, g_mid);

    // 1) qkv = x @ W_qkv
    sgemm64<<<dim3(THC / 64, (BB * NN) / 64), 256>>>(
        x, wqkv, (float*)p_qkv, BB * NN, THC, DIM);

    // 2) split + rotary + scale
    qkv_transform<<<(BB * HEADS * NN * 32) / 256, 256>>>();

    // 3) fused flash attention (tf32 tensor cores, +pos_bias, softmax)
    attn_tf32<<<dim3(NN / 128, HEADS, BB), 256>>>(bias);

    // 4) out = mid @ W_out
    sgemm64<<<dim3(DIM / 64, (BB * NN) / 64), 256>>>(
        (const float*)p_mid, wout, (float*)d_out, BB * NN, DIM, HIDDEN);
}

// round 7
// speedup vs baseline: 1.9813x; 1.0461x over previous
#include <cuda_runtime.h>
#include <math.h>

// Problem constants
#define BB 4
#define NN 2048
#define DIM 512
#define HEADS 8
#define DH 64
#define HIDDEN 512          // HEADS*DH
#define THC 1536            // 3*HIDDEN

// ---------------- scratch (device globals: allocation-free rule) ----------
__device__ float g_qkv[(size_t)BB * NN * THC];        // 48 MB
__device__ float g_q  [(size_t)BB * HEADS * NN * DH]; // 16 MB
__device__ float g_k  [(size_t)BB * HEADS * NN * DH]; // 16 MB
__device__ float g_v  [(size_t)BB * HEADS * NN * DH]; // 16 MB
__device__ float g_mid[(size_t)BB * NN * HIDDEN];     // 16 MB

// inv_freq[i] = 10000^(-2i/64) = 10^(-i/8), correctly-rounded fp32
__constant__ float c_invfreq[32] = {
    1.0f,
    0.74989420933245582f, 0.56234132519034907f, 0.42169650342858220f,
    0.31622776601683794f, 0.23713737056616552f, 0.17782794100389228f,
    0.13335214321633240f, 0.1f,
    0.074989420933245582f, 0.056234132519034907f, 0.042169650342858220f,
    0.031622776601683794f, 0.023713737056616552f, 0.017782794100389228f,
    0.013335214321633240f, 0.01f,
    0.0074989420933245582f, 0.0056234132519034907f, 0.0042169650342858220f,
    0.0031622776601683794f, 0.0023713737056616552f, 0.0017782794100389228f,
    0.0013335214321633240f, 0.001f,
    0.00074989420933245582f, 0.00056234132519034907f, 0.00042169650342858220f,
    0.00031622776601683794f, 0.00023713737056616552f, 0.00017782794100389228f,
    0.00013335214321633240f
};

// ---------------- tf32 / packed-f32 helpers ----------------
__device__ __forceinline__ unsigned cvt_tf32(float f) {
    unsigned r;
    asm("cvt.rna.tf32.f32 %0, %1;" : "=r"(r) : "f"(f));
    return r;
}

__device__ __forceinline__ void mma_tf32(float c[4],
                                         unsigned a0, unsigned a1,
                                         unsigned a2, unsigned a3,
                                         unsigned b0, unsigned b1) {
    asm volatile(
        "mma.sync.aligned.m16n8k8.row.col.f32.tf32.tf32.f32 "
        "{%0,%1,%2,%3}, {%4,%5,%6,%7}, {%8,%9}, {%0,%1,%2,%3};\n"
        : "+f"(c[0]), "+f"(c[1]), "+f"(c[2]), "+f"(c[3])
        : "r"(a0), "r"(a1), "r"(a2), "r"(a3), "r"(b0), "r"(b1));
}

__device__ __forceinline__ unsigned long long pack_dup(float v) {
    unsigned long long d;
    unsigned u = __float_as_uint(v);
    asm("mov.b64 %0, {%1, %1};" : "=l"(d) : "r"(u));
    return d;
}
__device__ __forceinline__ void ffma2(unsigned long long& acc,
                                      unsigned long long a,
                                      unsigned long long b) {
    asm("fma.rn.f32x2 %0, %1, %2, %0;" : "+l"(acc) : "l"(a), "l"(b));
}

// =====================================================================
// SGEMM (fp32-exact, packed FFMA2): C[M,Nc] = A[M,K] @ B[K,Nc].
// 128x64 tile, BK=16, 256 threads, 8x4 per thread (rows paired in f32x2).
// Ast stored k-major [k][m] stride 134 (even -> LDS.64-aligned pairs,
// 1072%32=16 -> conflict-free split stores).
// =====================================================================
__global__ __launch_bounds__(256)
void sgemm128(const float* __restrict__ A, const float* __restrict__ Bm,
              float* __restrict__ C, int M, int Nc, int K)
{
    __shared__ float Ast[16 * 134];
    __shared__ float Bs [16 * 64];

    const int tid = threadIdx.x;
    const int tx  = tid & 15;          // 4 cols
    const int ty  = tid >> 4;          // 8 rows
    const int m0  = blockIdx.y * 128;
    const int n0  = blockIdx.x * 64;

    unsigned long long acc[4][4];      // [col][row-pair]
#pragma unroll
    for (int j = 0; j < 4; ++j)
#pragma unroll
        for (int p = 0; p < 4; ++p) acc[j][p] = 0ULL;

    const int ar = tid >> 1;           // 0..127
    const int ks = (tid & 1) * 8;      // 0 or 8
    const int bk  = tid >> 4;
    const int bc4 = (tid & 15) * 4;

    for (int k0 = 0; k0 < K; k0 += 16) {
        float4 a0 = *(const float4*)&A[(size_t)(m0 + ar) * K + k0 + ks];
        float4 a1 = *(const float4*)&A[(size_t)(m0 + ar) * K + k0 + ks + 4];
        Ast[(ks + 0) * 134 + ar] = a0.x;
        Ast[(ks + 1) * 134 + ar] = a0.y;
        Ast[(ks + 2) * 134 + ar] = a0.z;
        Ast[(ks + 3) * 134 + ar] = a0.w;
        Ast[(ks + 4) * 134 + ar] = a1.x;
        Ast[(ks + 5) * 134 + ar] = a1.y;
        Ast[(ks + 6) * 134 + ar] = a1.z;
        Ast[(ks + 7) * 134 + ar] = a1.w;
        *(float4*)&Bs[bk * 64 + bc4] =
            *(const float4*)&Bm[(size_t)(k0 + bk) * Nc + n0 + bc4];
        __syncthreads();

#pragma unroll
        for (int k = 0; k < 16; ++k) {
            const float* arow = &Ast[k * 134 + ty * 8];
            unsigned long long ap0 = *(const unsigned long long*)(arow + 0);
            unsigned long long ap1 = *(const unsigned long long*)(arow + 2);
            unsigned long long ap2 = *(const unsigned long long*)(arow + 4);
            unsigned long long ap3 = *(const unsigned long long*)(arow + 6);
            float4 b = *(const float4*)&Bs[k * 64 + (tx << 2)];
            unsigned long long b0 = pack_dup(b.x);
            unsigned long long b1 = pack_dup(b.y);
            unsigned long long b2 = pack_dup(b.z);
            unsigned long long b3 = pack_dup(b.w);
            ffma2(acc[0][0], ap0, b0); ffma2(acc[0][1], ap1, b0);
            ffma2(acc[0][2], ap2, b0); ffma2(acc[0][3], ap3, b0);
            ffma2(acc[1][0], ap0, b1); ffma2(acc[1][1], ap1, b1);
            ffma2(acc[1][2], ap2, b1); ffma2(acc[1][3], ap3, b1);
            ffma2(acc[2][0], ap0, b2); ffma2(acc[2][1], ap1, b2);
            ffma2(acc[2][2], ap2, b2); ffma2(acc[2][3], ap3, b2);
            ffma2(acc[3][0], ap0, b3); ffma2(acc[3][1], ap1, b3);
            ffma2(acc[3][2], ap2, b3); ffma2(acc[3][3], ap3, b3);
        }
        __syncthreads();
    }

#pragma unroll
    for (int p = 0; p < 4; ++p) {
        float4 lo, hi;
        lo.x = __uint_as_float((unsigned)acc[0][p]);
        lo.y = __uint_as_float((unsigned)acc[1][p]);
        lo.z = __uint_as_float((unsigned)acc[2][p]);
        lo.w = __uint_as_float((unsigned)acc[3][p]);
        hi.x = __uint_as_float((unsigned)(acc[0][p] >> 32));
        hi.y = __uint_as_float((unsigned)(acc[1][p] >> 32));
        hi.z = __uint_as_float((unsigned)(acc[2][p] >> 32));
        hi.w = __uint_as_float((unsigned)(acc[3][p] >> 32));
        size_t r = (size_t)(m0 + ty * 8 + 2 * p);
        *(float4*)&C[r * Nc + n0 + (tx << 2)]       = lo;
        *(float4*)&C[(r + 1) * Nc + n0 + (tx << 2)] = hi;
    }
}

// =====================================================================
// QKV split + head reshape + rotary (+ q scale).
// =====================================================================
__global__ __launch_bounds__(256)
void qkv_transform()
{
    const int idx  = blockIdx.x * 256 + threadIdx.x;
    const int pair = idx & 31;
    const int n    = (idx >> 5) & (NN - 1);
    const int bh   = idx >> 16;
    const int b    = bh >> 3;
    const int h    = bh & 7;

    const float* src = g_qkv + (size_t)(b * NN + n) * THC;
    const int col = h * DH + pair * 2;

    float2 qv = *(const float2*)&src[col];
    float2 kv = *(const float2*)&src[HIDDEN + col];
    float2 vv = *(const float2*)&src[2 * HIDDEN + col];

    float fr = (float)n * c_invfreq[pair];
    float sn, cs;
    sincosf(fr, &sn, &cs);

    const float scale = 0.125f;
    float oq0 = (qv.x * cs - qv.y * sn) * scale;
    float oq1 = (qv.y * cs + qv.x * sn) * scale;
    float ok0 = kv.x * cs - kv.y * sn;
    float ok1 = kv.y * cs + kv.x * sn;

    size_t o = ((size_t)bh * NN + n) * DH + pair * 2;
    g_q[o] = oq0; g_q[o + 1] = oq1;
    g_k[o] = ok0; g_k[o + 1] = ok1;
    g_v[o] = vv.x; g_v[o + 1] = vv.y;
}

// =====================================================================
// Fused flash attention, tf32 tensor cores, software-pipelined.
// grid = (NN/128, HEADS, BB), block 256 (8 warps x 16 q rows).
// Chunk = 32 keys. Double-buffered fragment-major K/V smem:
//   slot s (= consuming lane) stride 20 words, +8 skew for s>=16, per-t
//   stride 656 words -> reader does 4x LDS.128 per (t), bank-conflict-free.
// Bias LDGs issued at iteration top directly into S accumulators.
// K/V for chunk j+1 prefetched (LDG) at top of j, stored (STS) mid-j.
// One __syncthreads per chunk.
// =====================================================================
#define TSTRIDE 656
__global__ __launch_bounds__(256, 2)
void attn_tf32(const float* __restrict__ bias)
{
    __shared__ unsigned KF[2][4 * TSTRIDE];
    __shared__ unsigned VF[2][4 * TSTRIDE];

    const int tid  = threadIdx.x;
    const int lane = tid & 31;
    const int w    = tid >> 5;
    const int qg   = lane >> 2;
    const int q    = lane & 3;
    const int qblk = blockIdx.x * 128;
    const int h    = blockIdx.y;
    const int b    = blockIdx.z;
    const size_t base = ((size_t)(b * HEADS + h)) * NN * DH;
    const float* biasw = bias + (size_t)h * NN * NN
                              + (size_t)(qblk + w * 16) * NN;

    // writer-side indices (per-thread fixed): 32x64 chunk, 8 vals each
    const int wr  = tid >> 3;            // key row in chunk (0..31)
    const int wc8 = (tid & 7) * 8;       // dh col base
    const int wt  = wr >> 3;             // t group
    const int wqg = wr & 7;
    const int wq  = wr & 3;
    const int whf = (wr >> 2) & 1;
    const int wkc = tid & 7;             // dh/8
    const int kdst = wt * TSTRIDE + wqg * 80 + (wqg >= 4 ? 8 : 0) + wkc * 2;
    const int vdst = wt * TSTRIDE + wq * 20 + wkc * 2 + whf;
    // reader base
    const int rb = lane * 20 + (lane >= 16 ? 8 : 0);

    // ---- Q fragments, register-resident ----
    unsigned qa[8][4];
    {
        const float* Qp = g_q + base + (size_t)(qblk + w * 16) * DH;
#pragma unroll
        for (int kc = 0; kc < 8; ++kc) {
            qa[kc][0] = cvt_tf32(Qp[(size_t)qg       * DH + kc * 8 + q]);
            qa[kc][1] = cvt_tf32(Qp[(size_t)(qg + 8) * DH + kc * 8 + q]);
            qa[kc][2] = cvt_tf32(Qp[(size_t)qg       * DH + kc * 8 + q + 4]);
            qa[kc][3] = cvt_tf32(Qp[(size_t)(qg + 8) * DH + kc * 8 + q + 4]);
        }
    }

    // ---- prologue: fill buffer 0 with chunk 0 ----
    {
        const float* kp = g_k + base + (size_t)wr * DH + wc8;
        const float* vp = g_v + base + (size_t)wr * DH + wc8;
        float4 k0 = *(const float4*)kp, k1 = *(const float4*)(kp + 4);
        float4 v0 = *(const float4*)vp, v1 = *(const float4*)(vp + 4);
        unsigned* kf = KF[0];
        unsigned* vf = VF[0];
        kf[kdst +  0] = cvt_tf32(k0.x); kf[kdst + 20] = cvt_tf32(k0.y);
        kf[kdst + 40] = cvt_tf32(k0.z); kf[kdst + 60] = cvt_tf32(k0.w);
        kf[kdst +  1] = cvt_tf32(k1.x); kf[kdst + 21] = cvt_tf32(k1.y);
        kf[kdst + 41] = cvt_tf32(k1.z); kf[kdst + 61] = cvt_tf32(k1.w);
        vf[vdst +   0]      = cvt_tf32(v0.x);
        vf[vdst +  80]      = cvt_tf32(v0.y);
        vf[vdst + 160]      = cvt_tf32(v0.z);
        vf[vdst + 240]      = cvt_tf32(v0.w);
        vf[vdst + 320 + 8]  = cvt_tf32(v1.x);
        vf[vdst + 400 + 8]  = cvt_tf32(v1.y);
        vf[vdst + 480 + 8]  = cvt_tf32(v1.z);
        vf[vdst + 560 + 8]  = cvt_tf32(v1.w);
    }
    __syncthreads();

    float O[8][4];
#pragma unroll
    for (int n = 0; n < 8; ++n)
#pragma unroll
        for (int j = 0; j < 4; ++j) O[n][j] = 0.f;
    float m0 = -INFINITY, m1 = -INFINITY, l0 = 0.f, l1 = 0.f;

    int p = 0;
    for (int j = 0; j < 64; ++j) {
        // ---- prefetch next chunk (LDG only; consumed after softmax) ----
        const int jn = (j + 1 < 64) ? j + 1 : 63;
        const float* kp = g_k + base + (size_t)(jn * 32 + wr) * DH + wc8;
        const float* vp = g_v + base + (size_t)(jn * 32 + wr) * DH + wc8;
        float4 kn0 = *(const float4*)kp, kn1 = *(const float4*)(kp + 4);
        float4 vn0 = *(const float4*)vp, vn1 = *(const float4*)(vp + 4);

        const int j0 = j * 32;

        // ---- S = bias (LDG latency covered by S-phase mma below) ----
        float S[4][4];
#pragma unroll
        for (int t = 0; t < 4; ++t) {
            float2 blo = *(const float2*)
                &biasw[(size_t)qg       * NN + j0 + t * 8 + 2 * q];
            float2 bhi = *(const float2*)
                &biasw[(size_t)(qg + 8) * NN + j0 + t * 8 + 2 * q];
            S[t][0] = blo.x; S[t][1] = blo.y;
            S[t][2] = bhi.x; S[t][3] = bhi.y;
        }

        // ---- S += Q K^T (fragment-major K, 4x LDS.128 per t) ----
        const unsigned* kfp = KF[p];
#pragma unroll
        for (int t = 0; t < 4; ++t) {
            const uint4* kk = (const uint4*)&kfp[t * TSTRIDE + rb];
            uint4 k0 = kk[0], k1 = kk[1], k2 = kk[2], k3 = kk[3];
            mma_tf32(S[t], qa[0][0], qa[0][1], qa[0][2], qa[0][3], k0.x, k0.y);
            mma_tf32(S[t], qa[1][0], qa[1][1], qa[1][2], qa[1][3], k0.z, k0.w);
            mma_tf32(S[t], qa[2][0], qa[2][1], qa[2][2], qa[2][3], k1.x, k1.y);
            mma_tf32(S[t], qa[3][0], qa[3][1], qa[3][2], qa[3][3], k1.z, k1.w);
            mma_tf32(S[t], qa[4][0], qa[4][1], qa[4][2], qa[4][3], k2.x, k2.y);
            mma_tf32(S[t], qa[5][0], qa[5][1], qa[5][2], qa[5][3], k2.z, k2.w);
            mma_tf32(S[t], qa[6][0], qa[6][1], qa[6][2], qa[6][3], k3.x, k3.y);
            mma_tf32(S[t], qa[7][0], qa[7][1], qa[7][2], qa[7][3], k3.z, k3.w);
        }

        // ---- online softmax ----
        float cm0 = -INFINITY, cm1 = -INFINITY;
#pragma unroll
        for (int t = 0; t < 4; ++t) {
            cm0 = fmaxf(cm0, fmaxf(S[t][0], S[t][1]));
            cm1 = fmaxf(cm1, fmaxf(S[t][2], S[t][3]));
        }
        cm0 = fmaxf(cm0, __shfl_xor_sync(0xffffffffu, cm0, 1));
        cm0 = fmaxf(cm0, __shfl_xor_sync(0xffffffffu, cm0, 2));
        cm1 = fmaxf(cm1, __shfl_xor_sync(0xffffffffu, cm1, 1));
        cm1 = fmaxf(cm1, __shfl_xor_sync(0xffffffffu, cm1, 2));

        float mn0 = fmaxf(m0, cm0), mn1 = fmaxf(m1, cm1);
        float al0 = __expf(m0 - mn0), al1 = __expf(m1 - mn1);
        m0 = mn0; m1 = mn1;

        float s0 = 0.f, s1 = 0.f;
#pragma unroll
        for (int t = 0; t < 4; ++t) {
            S[t][0] = __expf(S[t][0] - mn0);
            S[t][1] = __expf(S[t][1] - mn0);
            S[t][2] = __expf(S[t][2] - mn1);
            S[t][3] = __expf(S[t][3] - mn1);
            s0 += S[t][0] + S[t][1];
            s1 += S[t][2] + S[t][3];
        }
        s0 += __shfl_xor_sync(0xffffffffu, s0, 1);
        s0 += __shfl_xor_sync(0xffffffffu, s0, 2);
        s1 += __shfl_xor_sync(0xffffffffu, s1, 1);
        s1 += __shfl_xor_sync(0xffffffffu, s1, 2);
        l0 = l0 * al0 + s0;
        l1 = l1 * al1 + s1;
#pragma unroll
        for (int n = 0; n < 8; ++n) {
            O[n][0] *= al0; O[n][1] *= al0;
            O[n][2] *= al1; O[n][3] *= al1;
        }

        // ---- store prefetched chunk into the other buffer ----
        {
            unsigned* kf = KF[p ^ 1];
            unsigned* vf = VF[p ^ 1];
            kf[kdst +  0] = cvt_tf32(kn0.x); kf[kdst + 20] = cvt_tf32(kn0.y);
            kf[kdst + 40] = cvt_tf32(kn0.z); kf[kdst + 60] = cvt_tf32(kn0.w);
            kf[kdst +  1] = cvt_tf32(kn1.x); kf[kdst + 21] = cvt_tf32(kn1.y);
            kf[kdst + 41] = cvt_tf32(kn1.z); kf[kdst + 61] = cvt_tf32(kn1.w);
            vf[vdst +   0]     = cvt_tf32(vn0.x);
            vf[vdst +  80]     = cvt_tf32(vn0.y);
            vf[vdst + 160]     = cvt_tf32(vn0.z);
            vf[vdst + 240]     = cvt_tf32(vn0.w);
            vf[vdst + 320 + 8] = cvt_tf32(vn1.x);
            vf[vdst + 400 + 8] = cvt_tf32(vn1.y);
            vf[vdst + 480 + 8] = cvt_tf32(vn1.z);
            vf[vdst + 560 + 8] = cvt_tf32(vn1.w);
        }

        // ---- O += P @ V (P re-fragmented via quad shuffles) ----
        const unsigned* vfp = VF[p];
        const int srcA = (lane & ~3) | (q >> 1);
        const int srcB = srcA | 2;
#pragma unroll
        for (int t = 0; t < 4; ++t) {
            unsigned p0 = cvt_tf32(S[t][0]);
            unsigned p1 = cvt_tf32(S[t][1]);
            unsigned p2 = cvt_tf32(S[t][2]);
            unsigned p3 = cvt_tf32(S[t][3]);
            unsigned u0 = __shfl_sync(0xffffffffu, p0, srcA);
            unsigned u1 = __shfl_sync(0xffffffffu, p1, srcA);
            unsigned v0s = __shfl_sync(0xffffffffu, p0, srcB);
            unsigned v1s = __shfl_sync(0xffffffffu, p1, srcB);
            unsigned w0 = __shfl_sync(0xffffffffu, p2, srcA);
            unsigned w1 = __shfl_sync(0xffffffffu, p3, srcA);
            unsigned x0 = __shfl_sync(0xffffffffu, p2, srcB);
            unsigned x1 = __shfl_sync(0xffffffffu, p3, srcB);
            unsigned a0 = (q & 1) ? u1 : u0;
            unsigned a1 = (q & 1) ? w1 : w0;
            unsigned a2 = (q & 1) ? v1s : v0s;
            unsigned a3 = (q & 1) ? x1 : x0;
            const uint4* vv = (const uint4*)&vfp[t * TSTRIDE + rb];
            uint4 v0 = vv[0], v1 = vv[1], v2 = vv[2], v3 = vv[3];
            mma_tf32(O[0], a0, a1, a2, a3, v0.x, v0.y);
            mma_tf32(O[1], a0, a1, a2, a3, v0.z, v0.w);
            mma_tf32(O[2], a0, a1, a2, a3, v1.x, v1.y);
            mma_tf32(O[3], a0, a1, a2, a3, v1.z, v1.w);
            mma_tf32(O[4], a0, a1, a2, a3, v2.x, v2.y);
            mma_tf32(O[5], a0, a1, a2, a3, v2.z, v2.w);
            mma_tf32(O[6], a0, a1, a2, a3, v3.x, v3.y);
            mma_tf32(O[7], a0, a1, a2, a3, v3.z, v3.w);
        }

        __syncthreads();
        p ^= 1;
    }

    // ---- finalize: /l, write to g_mid[b, n, h*64 + c] ----
    const float il0 = 1.f / l0, il1 = 1.f / l1;
    const int row0 = qblk + w * 16 + qg;
    const int row1 = row0 + 8;
#pragma unroll
    for (int n = 0; n < 8; ++n) {
        float2 olo = make_float2(O[n][0] * il0, O[n][1] * il0);
        float2 ohi = make_float2(O[n][2] * il1, O[n][3] * il1);
        *(float2*)&g_mid[(size_t)(b * NN + row0) * HIDDEN
                         + h * DH + n * 8 + 2 * q] = olo;
        *(float2*)&g_mid[(size_t)(b * NN + row1) * HIDDEN
                         + h * DH + n * 8 + 2 * q] = ohi;
    }
}

// =====================================================================
extern "C" void kernel_launch(void* const* d_in, const int* in_sizes, int n_in,
                              void* d_out, int out_size)
{
    const float *x = nullptr, *bias = nullptr, *wqkv = nullptr, *wout = nullptr;
    for (int i = 0; i < n_in; ++i) {
        switch (in_sizes[i]) {
            case 4194304:  x    = (const float*)d_in[i]; break;  // x [4,2048,512]
            case 33554432: bias = (const float*)d_in[i]; break;  // pos_bias [8,2048,2048]
            case 786432:   wqkv = (const float*)d_in[i]; break;  // W_qkv [512,1536]
            case 262144:   wout = (const float*)d_in[i]; break;  // W_out [512,512]
        }
    }

    void *p_qkv = nullptr, *p_mid = nullptr;
    cudaGetSymbolAddress(&p_qkv, g_qkv);
    cudaGetSymbolAddress(&p_mid, g_mid);

    // 1) qkv = x @ W_qkv
    sgemm128<<<dim3(THC / 64, (BB * NN) / 128), 256>>>(
        x, wqkv, (float*)p_qkv, BB * NN, THC, DIM);

    // 2) split + rotary + scale
    qkv_transform<<<(BB * HEADS * NN * 32) / 256, 256>>>();

    // 3) fused flash attention (tf32 tensor cores, pipelined)
    attn_tf32<<<dim3(NN / 128, HEADS, BB), 256>>>(bias);

    // 4) out = mid @ W_out
    sgemm128<<<dim3(DIM / 64, (BB * NN) / 128), 256>>>(
        (const float*)p_mid, wout, (float*)d_out, BB * NN, DIM, HIDDEN);
}

// round 8
// speedup vs baseline: 2.0372x; 1.0282x over previous
#include <cuda_runtime.h>
#include <math.h>

// Problem constants
#define BB 4
#define NN 2048
#define DIM 512
#define HEADS 8
#define DH 64
#define HIDDEN 512          // HEADS*DH
#define THC 1536            // 3*HIDDEN

// ---------------- scratch (device globals: allocation-free rule) ----------
__device__ float g_qkv[(size_t)BB * NN * THC];        // 48 MB
__device__ float g_q  [(size_t)BB * HEADS * NN * DH]; // 16 MB
__device__ float g_k  [(size_t)BB * HEADS * NN * DH]; // 16 MB
__device__ float g_v  [(size_t)BB * HEADS * NN * DH]; // 16 MB
__device__ float g_mid[(size_t)BB * NN * HIDDEN];     // 16 MB

// inv_freq[i] = 10000^(-2i/64) = 10^(-i/8), correctly-rounded fp32
__constant__ float c_invfreq[32] = {
    1.0f,
    0.74989420933245582f, 0.56234132519034907f, 0.42169650342858220f,
    0.31622776601683794f, 0.23713737056616552f, 0.17782794100389228f,
    0.13335214321633240f, 0.1f,
    0.074989420933245582f, 0.056234132519034907f, 0.042169650342858220f,
    0.031622776601683794f, 0.023713737056616552f, 0.017782794100389228f,
    0.013335214321633240f, 0.01f,
    0.0074989420933245582f, 0.0056234132519034907f, 0.0042169650342858220f,
    0.0031622776601683794f, 0.0023713737056616552f, 0.0017782794100389228f,
    0.0013335214321633240f, 0.001f,
    0.00074989420933245582f, 0.00056234132519034907f, 0.00042169650342858220f,
    0.00031622776601683794f, 0.00023713737056616552f, 0.00017782794100389228f,
    0.00013335214321633240f
};

// ---------------- tf32 / packed-f32 helpers ----------------
__device__ __forceinline__ unsigned cvt_tf32(float f) {
    unsigned r;
    asm("cvt.rna.tf32.f32 %0, %1;" : "=r"(r) : "f"(f));
    return r;
}

__device__ __forceinline__ void mma_tf32(float c[4],
                                         unsigned a0, unsigned a1,
                                         unsigned a2, unsigned a3,
                                         unsigned b0, unsigned b1) {
    asm volatile(
        "mma.sync.aligned.m16n8k8.row.col.f32.tf32.tf32.f32 "
        "{%0,%1,%2,%3}, {%4,%5,%6,%7}, {%8,%9}, {%0,%1,%2,%3};\n"
        : "+f"(c[0]), "+f"(c[1]), "+f"(c[2]), "+f"(c[3])
        : "r"(a0), "r"(a1), "r"(a2), "r"(a3), "r"(b0), "r"(b1));
}

__device__ __forceinline__ unsigned long long pack_dup(float v) {
    unsigned long long d;
    unsigned u = __float_as_uint(v);
    asm("mov.b64 %0, {%1, %1};" : "=l"(d) : "r"(u));
    return d;
}
__device__ __forceinline__ void ffma2(unsigned long long& acc,
                                      unsigned long long a,
                                      unsigned long long b) {
    asm("fma.rn.f32x2 %0, %1, %2, %0;" : "+l"(acc) : "l"(a), "l"(b));
}

__device__ __forceinline__ void cp16(float* dst_smem, const float* src_gmem) {
    unsigned s = (unsigned)__cvta_generic_to_shared(dst_smem);
    asm volatile("cp.async.cg.shared.global [%0], [%1], 16;"
                 :: "r"(s), "l"(src_gmem));
}
__device__ __forceinline__ void cp_commit() {
    asm volatile("cp.async.commit_group;");
}
__device__ __forceinline__ void cp_wait1() {
    asm volatile("cp.async.wait_group 1;");
}

// =====================================================================
// SGEMM (fp32-exact, packed FFMA2): C[M,Nc] = A[M,K] @ B[K,Nc].
// 128x64 tile, BK=16, 256 threads, 8x4 per thread (rows paired in f32x2).
// =====================================================================
__global__ __launch_bounds__(256)
void sgemm128(const float* __restrict__ A, const float* __restrict__ Bm,
              float* __restrict__ C, int M, int Nc, int K)
{
    __shared__ float Ast[16 * 134];
    __shared__ float Bs [16 * 64];

    const int tid = threadIdx.x;
    const int tx  = tid & 15;
    const int ty  = tid >> 4;
    const int m0  = blockIdx.y * 128;
    const int n0  = blockIdx.x * 64;

    unsigned long long acc[4][4];
#pragma unroll
    for (int j = 0; j < 4; ++j)
#pragma unroll
        for (int p = 0; p < 4; ++p) acc[j][p] = 0ULL;

    const int ar = tid >> 1;
    const int ks = (tid & 1) * 8;
    const int bk  = tid >> 4;
    const int bc4 = (tid & 15) * 4;

    for (int k0 = 0; k0 < K; k0 += 16) {
        float4 a0 = *(const float4*)&A[(size_t)(m0 + ar) * K + k0 + ks];
        float4 a1 = *(const float4*)&A[(size_t)(m0 + ar) * K + k0 + ks + 4];
        Ast[(ks + 0) * 134 + ar] = a0.x;
        Ast[(ks + 1) * 134 + ar] = a0.y;
        Ast[(ks + 2) * 134 + ar] = a0.z;
        Ast[(ks + 3) * 134 + ar] = a0.w;
        Ast[(ks + 4) * 134 + ar] = a1.x;
        Ast[(ks + 5) * 134 + ar] = a1.y;
        Ast[(ks + 6) * 134 + ar] = a1.z;
        Ast[(ks + 7) * 134 + ar] = a1.w;
        *(float4*)&Bs[bk * 64 + bc4] =
            *(const float4*)&Bm[(size_t)(k0 + bk) * Nc + n0 + bc4];
        __syncthreads();

#pragma unroll
        for (int k = 0; k < 16; ++k) {
            const float* arow = &Ast[k * 134 + ty * 8];
            unsigned long long ap0 = *(const unsigned long long*)(arow + 0);
            unsigned long long ap1 = *(const unsigned long long*)(arow + 2);
            unsigned long long ap2 = *(const unsigned long long*)(arow + 4);
            unsigned long long ap3 = *(const unsigned long long*)(arow + 6);
            float4 b = *(const float4*)&Bs[k * 64 + (tx << 2)];
            unsigned long long b0 = pack_dup(b.x);
            unsigned long long b1 = pack_dup(b.y);
            unsigned long long b2 = pack_dup(b.z);
            unsigned long long b3 = pack_dup(b.w);
            ffma2(acc[0][0], ap0, b0); ffma2(acc[0][1], ap1, b0);
            ffma2(acc[0][2], ap2, b0); ffma2(acc[0][3], ap3, b0);
            ffma2(acc[1][0], ap0, b1); ffma2(acc[1][1], ap1, b1);
            ffma2(acc[1][2], ap2, b1); ffma2(acc[1][3], ap3, b1);
            ffma2(acc[2][0], ap0, b2); ffma2(acc[2][1], ap1, b2);
            ffma2(acc[2][2], ap2, b2); ffma2(acc[2][3], ap3, b2);
            ffma2(acc[3][0], ap0, b3); ffma2(acc[3][1], ap1, b3);
            ffma2(acc[3][2], ap2, b3); ffma2(acc[3][3], ap3, b3);
        }
        __syncthreads();
    }

#pragma unroll
    for (int p = 0; p < 4; ++p) {
        float4 lo, hi;
        lo.x = __uint_as_float((unsigned)acc[0][p]);
        lo.y = __uint_as_float((unsigned)acc[1][p]);
        lo.z = __uint_as_float((unsigned)acc[2][p]);
        lo.w = __uint_as_float((unsigned)acc[3][p]);
        hi.x = __uint_as_float((unsigned)(acc[0][p] >> 32));
        hi.y = __uint_as_float((unsigned)(acc[1][p] >> 32));
        hi.z = __uint_as_float((unsigned)(acc[2][p] >> 32));
        hi.w = __uint_as_float((unsigned)(acc[3][p] >> 32));
        size_t r = (size_t)(m0 + ty * 8 + 2 * p);
        *(float4*)&C[r * Nc + n0 + (tx << 2)]       = lo;
        *(float4*)&C[(r + 1) * Nc + n0 + (tx << 2)] = hi;
    }
}

// =====================================================================
// QKV split + head reshape + rotary (+ q scale).
// =====================================================================
__global__ __launch_bounds__(256)
void qkv_transform()
{
    const int idx  = blockIdx.x * 256 + threadIdx.x;
    const int pair = idx & 31;
    const int n    = (idx >> 5) & (NN - 1);
    const int bh   = idx >> 16;
    const int b    = bh >> 3;
    const int h    = bh & 7;

    const float* src = g_qkv + (size_t)(b * NN + n) * THC;
    const int col = h * DH + pair * 2;

    float2 qv = *(const float2*)&src[col];
    float2 kv = *(const float2*)&src[HIDDEN + col];
    float2 vv = *(const float2*)&src[2 * HIDDEN + col];

    float fr = (float)n * c_invfreq[pair];
    float sn, cs;
    sincosf(fr, &sn, &cs);

    const float scale = 0.125f;
    float oq0 = (qv.x * cs - qv.y * sn) * scale;
    float oq1 = (qv.y * cs + qv.x * sn) * scale;
    float ok0 = kv.x * cs - kv.y * sn;
    float ok1 = kv.y * cs + kv.x * sn;

    size_t o = ((size_t)bh * NN + n) * DH + pair * 2;
    g_q[o] = oq0; g_q[o + 1] = oq1;
    g_k[o] = ok0; g_k[o + 1] = ok1;
    g_v[o] = vv.x; g_v[o + 1] = vv.y;
}

// =====================================================================
// Fused flash attention, tf32 tensor cores, cp.async pipelined.
// grid = (NN/128, HEADS, BB), block 256 (8 warps x 16 q rows), chunk = 32.
//
// Per iteration j:  compute chunk j (frag[j&1], S pre-loaded with bias) |
//   cp.async chunk j+2 -> stg[j&1] | wait_group(1) | bias(j+1) -> S |
//   repack stg[(j+1)&1] -> frag[(j+1)&1] (own bytes only: no barrier
//   needed for staging) | one __syncthreads.
// Registers: no LDG prefetch staging, no spills (target <=128 @ 2 blk/SM).
// Dynamic smem 76.8KB/block: KF/VF fragment-major double buffers +
// fp32 staging (stride 68, 16B-aligned rows for cp.async).
// =====================================================================
#define TSTRIDE 656
#define SSTRIDE 68
#define STG_CHUNK (32 * SSTRIDE)

__global__ __launch_bounds__(256, 2)
void attn_tf32(const float* __restrict__ bias)
{
    extern __shared__ unsigned smem_u[];
    unsigned* KF  = smem_u;                      // [2][4*TSTRIDE]
    unsigned* VF  = smem_u + 2 * 4 * TSTRIDE;    // [2][4*TSTRIDE]
    float*    stK = (float*)(smem_u + 4 * 4 * TSTRIDE);  // [2][32*68]
    float*    stV = stK + 2 * STG_CHUNK;                  // [2][32*68]

    const int tid  = threadIdx.x;
    const int lane = tid & 31;
    const int w    = tid >> 5;
    const int qg   = lane >> 2;
    const int q    = lane & 3;
    const int qblk = blockIdx.x * 128;
    const int h    = blockIdx.y;
    const int b    = blockIdx.z;
    const size_t base = ((size_t)(b * HEADS + h)) * NN * DH;
    const float* gk = g_k + base;
    const float* gv = g_v + base;
    const float* biasw = bias + (size_t)h * NN * NN
                              + (size_t)(qblk + w * 16) * NN;

    // writer-side indices: thread owns K/V row wr, cols [wc8, wc8+8)
    const int wr  = tid >> 3;
    const int wc8 = (tid & 7) * 8;
    const int wt  = wr >> 3;
    const int wqg = wr & 7;
    const int wq  = wr & 3;
    const int whf = (wr >> 2) & 1;
    const int wkc = tid & 7;
    const int kdst = wt * TSTRIDE + wqg * 80 + (wqg >= 4 ? 8 : 0) + wkc * 2;
    const int vdst = wt * TSTRIDE + wq * 20 + wkc * 2 + whf;
    const int stoff = wr * SSTRIDE + wc8;        // staging offset (own bytes)
    const int rb = lane * 20 + (lane >= 16 ? 8 : 0);   // reader base

    // ---- Q fragments, register-resident ----
    unsigned qa[8][4];
    {
        const float* Qp = g_q + base + (size_t)(qblk + w * 16) * DH;
#pragma unroll
        for (int kc = 0; kc < 8; ++kc) {
            qa[kc][0] = cvt_tf32(Qp[(size_t)qg       * DH + kc * 8 + q]);
            qa[kc][1] = cvt_tf32(Qp[(size_t)(qg + 8) * DH + kc * 8 + q]);
            qa[kc][2] = cvt_tf32(Qp[(size_t)qg       * DH + kc * 8 + q + 4]);
            qa[kc][3] = cvt_tf32(Qp[(size_t)(qg + 8) * DH + kc * 8 + q + 4]);
        }
    }

    // ---- prologue: stage chunks 0 and 1, repack chunk 0, bias chunk 0 ----
    cp16(&stK[stoff], gk + (size_t)wr * DH + wc8);
    cp16(&stK[stoff + 4], gk + (size_t)wr * DH + wc8 + 4);
    cp16(&stV[stoff], gv + (size_t)wr * DH + wc8);
    cp16(&stV[stoff + 4], gv + (size_t)wr * DH + wc8 + 4);
    cp_commit();
    cp16(&stK[STG_CHUNK + stoff], gk + (size_t)(32 + wr) * DH + wc8);
    cp16(&stK[STG_CHUNK + stoff + 4], gk + (size_t)(32 + wr) * DH + wc8 + 4);
    cp16(&stV[STG_CHUNK + stoff], gv + (size_t)(32 + wr) * DH + wc8);
    cp16(&stV[STG_CHUNK + stoff + 4], gv + (size_t)(32 + wr) * DH + wc8 + 4);
    cp_commit();

    float S[4][4];
    cp_wait1();   // chunk 0 staged (this thread's bytes)
    {
        // bias chunk 0 -> S
#pragma unroll
        for (int t = 0; t < 4; ++t) {
            float2 blo = *(const float2*)&biasw[(size_t)qg       * NN + t * 8 + 2 * q];
            float2 bhi = *(const float2*)&biasw[(size_t)(qg + 8) * NN + t * 8 + 2 * q];
            S[t][0] = blo.x; S[t][1] = blo.y;
            S[t][2] = bhi.x; S[t][3] = bhi.y;
        }
        // repack chunk 0 -> frag 0
        float4 k0 = *(const float4*)&stK[stoff];
        float4 k1 = *(const float4*)&stK[stoff + 4];
        float4 v0 = *(const float4*)&stV[stoff];
        float4 v1 = *(const float4*)&stV[stoff + 4];
        unsigned* kf = KF;
        unsigned* vf = VF;
        kf[kdst +  0] = cvt_tf32(k0.x); kf[kdst + 20] = cvt_tf32(k0.y);
        kf[kdst + 40] = cvt_tf32(k0.z); kf[kdst + 60] = cvt_tf32(k0.w);
        kf[kdst +  1] = cvt_tf32(k1.x); kf[kdst + 21] = cvt_tf32(k1.y);
        kf[kdst + 41] = cvt_tf32(k1.z); kf[kdst + 61] = cvt_tf32(k1.w);
        vf[vdst +   0]     = cvt_tf32(v0.x);
        vf[vdst +  80]     = cvt_tf32(v0.y);
        vf[vdst + 160]     = cvt_tf32(v0.z);
        vf[vdst + 240]     = cvt_tf32(v0.w);
        vf[vdst + 320 + 8] = cvt_tf32(v1.x);
        vf[vdst + 400 + 8] = cvt_tf32(v1.y);
        vf[vdst + 480 + 8] = cvt_tf32(v1.z);
        vf[vdst + 560 + 8] = cvt_tf32(v1.w);
    }
    __syncthreads();

    float O[8][4];
#pragma unroll
    for (int n = 0; n < 8; ++n)
#pragma unroll
        for (int j = 0; j < 4; ++j) O[n][j] = 0.f;
    float m0 = -INFINITY, m1 = -INFINITY, l0 = 0.f, l1 = 0.f;

    for (int j = 0; j < 64; ++j) {
        const int p = j & 1;

        // ---- S += Q K^T (S pre-loaded with bias) ----
        const unsigned* kfp = KF + p * (4 * TSTRIDE);
#pragma unroll
        for (int t = 0; t < 4; ++t) {
            const uint4* kk = (const uint4*)&kfp[t * TSTRIDE + rb];
            uint4 k0 = kk[0], k1 = kk[1], k2 = kk[2], k3 = kk[3];
            mma_tf32(S[t], qa[0][0], qa[0][1], qa[0][2], qa[0][3], k0.x, k0.y);
            mma_tf32(S[t], qa[1][0], qa[1][1], qa[1][2], qa[1][3], k0.z, k0.w);
            mma_tf32(S[t], qa[2][0], qa[2][1], qa[2][2], qa[2][3], k1.x, k1.y);
            mma_tf32(S[t], qa[3][0], qa[3][1], qa[3][2], qa[3][3], k1.z, k1.w);
            mma_tf32(S[t], qa[4][0], qa[4][1], qa[4][2], qa[4][3], k2.x, k2.y);
            mma_tf32(S[t], qa[5][0], qa[5][1], qa[5][2], qa[5][3], k2.z, k2.w);
            mma_tf32(S[t], qa[6][0], qa[6][1], qa[6][2], qa[6][3], k3.x, k3.y);
            mma_tf32(S[t], qa[7][0], qa[7][1], qa[7][2], qa[7][3], k3.z, k3.w);
        }

        // ---- online softmax ----
        float cm0 = -INFINITY, cm1 = -INFINITY;
#pragma unroll
        for (int t = 0; t < 4; ++t) {
            cm0 = fmaxf(cm0, fmaxf(S[t][0], S[t][1]));
            cm1 = fmaxf(cm1, fmaxf(S[t][2], S[t][3]));
        }
        cm0 = fmaxf(cm0, __shfl_xor_sync(0xffffffffu, cm0, 1));
        cm0 = fmaxf(cm0, __shfl_xor_sync(0xffffffffu, cm0, 2));
        cm1 = fmaxf(cm1, __shfl_xor_sync(0xffffffffu, cm1, 1));
        cm1 = fmaxf(cm1, __shfl_xor_sync(0xffffffffu, cm1, 2));

        float mn0 = fmaxf(m0, cm0), mn1 = fmaxf(m1, cm1);
        float al0 = __expf(m0 - mn0), al1 = __expf(m1 - mn1);
        m0 = mn0; m1 = mn1;

        float s0 = 0.f, s1 = 0.f;
#pragma unroll
        for (int t = 0; t < 4; ++t) {
            S[t][0] = __expf(S[t][0] - mn0);
            S[t][1] = __expf(S[t][1] - mn0);
            S[t][2] = __expf(S[t][2] - mn1);
            S[t][3] = __expf(S[t][3] - mn1);
            s0 += S[t][0] + S[t][1];
            s1 += S[t][2] + S[t][3];
        }
        s0 += __shfl_xor_sync(0xffffffffu, s0, 1);
        s0 += __shfl_xor_sync(0xffffffffu, s0, 2);
        s1 += __shfl_xor_sync(0xffffffffu, s1, 1);
        s1 += __shfl_xor_sync(0xffffffffu, s1, 2);
        l0 = l0 * al0 + s0;
        l1 = l1 * al1 + s1;
#pragma unroll
        for (int n = 0; n < 8; ++n) {
            O[n][0] *= al0; O[n][1] *= al0;
            O[n][2] *= al1; O[n][3] *= al1;
        }

        // ---- O += P @ V (P re-fragmented via quad shuffles) ----
        const unsigned* vfp = VF + p * (4 * TSTRIDE);
        const int srcA = (lane & ~3) | (q >> 1);
        const int srcB = srcA | 2;
#pragma unroll
        for (int t = 0; t < 4; ++t) {
            unsigned p0 = cvt_tf32(S[t][0]);
            unsigned p1 = cvt_tf32(S[t][1]);
            unsigned p2 = cvt_tf32(S[t][2]);
            unsigned p3 = cvt_tf32(S[t][3]);
            unsigned u0 = __shfl_sync(0xffffffffu, p0, srcA);
            unsigned u1 = __shfl_sync(0xffffffffu, p1, srcA);
            unsigned v0s = __shfl_sync(0xffffffffu, p0, srcB);
            unsigned v1s = __shfl_sync(0xffffffffu, p1, srcB);
            unsigned w0 = __shfl_sync(0xffffffffu, p2, srcA);
            unsigned w1 = __shfl_sync(0xffffffffu, p3, srcA);
            unsigned x0 = __shfl_sync(0xffffffffu, p2, srcB);
            unsigned x1 = __shfl_sync(0xffffffffu, p3, srcB);
            unsigned a0 = (q & 1) ? u1 : u0;
            unsigned a1 = (q & 1) ? w1 : w0;
            unsigned a2 = (q & 1) ? v1s : v0s;
            unsigned a3 = (q & 1) ? x1 : x0;
            const uint4* vv = (const uint4*)&vfp[t * TSTRIDE + rb];
            uint4 v0 = vv[0], v1 = vv[1], v2 = vv[2], v3 = vv[3];
            mma_tf32(O[0], a0, a1, a2, a3, v0.x, v0.y);
            mma_tf32(O[1], a0, a1, a2, a3, v0.z, v0.w);
            mma_tf32(O[2], a0, a1, a2, a3, v1.x, v1.y);
            mma_tf32(O[3], a0, a1, a2, a3, v1.z, v1.w);
            mma_tf32(O[4], a0, a1, a2, a3, v2.x, v2.y);
            mma_tf32(O[5], a0, a1, a2, a3, v2.z, v2.w);
            mma_tf32(O[6], a0, a1, a2, a3, v3.x, v3.y);
            mma_tf32(O[7], a0, a1, a2, a3, v3.z, v3.w);
        }

        // ---- stage chunk j+2 into stg[j&1] (clamped; uniform groups) ----
        {
            const int jc = (j + 2 < 64) ? j + 2 : 63;
            const size_t roff = (size_t)(jc * 32 + wr) * DH + wc8;
            float* sk = &stK[p * STG_CHUNK + stoff];
            float* sv = &stV[p * STG_CHUNK + stoff];
            cp16(sk,     gk + roff);
            cp16(sk + 4, gk + roff + 4);
            cp16(sv,     gv + roff);
            cp16(sv + 4, gv + roff + 4);
            cp_commit();
        }
        cp_wait1();   // chunk j+1 staged (own bytes)

        // ---- bias chunk j+1 -> S (latency hidden behind repack+sync) ----
        {
            const int jb = (j + 1 < 64) ? j + 1 : 63;
            const int j0n = jb * 32;
#pragma unroll
            for (int t = 0; t < 4; ++t) {
                float2 blo = *(const float2*)
                    &biasw[(size_t)qg       * NN + j0n + t * 8 + 2 * q];
                float2 bhi = *(const float2*)
                    &biasw[(size_t)(qg + 8) * NN + j0n + t * 8 + 2 * q];
                S[t][0] = blo.x; S[t][1] = blo.y;
                S[t][2] = bhi.x; S[t][3] = bhi.y;
            }
        }

        // ---- repack chunk j+1: stg[(j+1)&1] -> frag[(j+1)&1] ----
        {
            const int pn = p ^ 1;
            const float* sk = &stK[pn * STG_CHUNK + stoff];
            const float* sv = &stV[pn * STG_CHUNK + stoff];
            float4 k0 = *(const float4*)sk;
            float4 k1 = *(const float4*)(sk + 4);
            float4 v0 = *(const float4*)sv;
            float4 v1 = *(const float4*)(sv + 4);
            unsigned* kf = KF + pn * (4 * TSTRIDE);
            unsigned* vf = VF + pn * (4 * TSTRIDE);
            kf[kdst +  0] = cvt_tf32(k0.x); kf[kdst + 20] = cvt_tf32(k0.y);
            kf[kdst + 40] = cvt_tf32(k0.z); kf[kdst + 60] = cvt_tf32(k0.w);
            kf[kdst +  1] = cvt_tf32(k1.x); kf[kdst + 21] = cvt_tf32(k1.y);
            kf[kdst + 41] = cvt_tf32(k1.z); kf[kdst + 61] = cvt_tf32(k1.w);
            vf[vdst +   0]     = cvt_tf32(v0.x);
            vf[vdst +  80]     = cvt_tf32(v0.y);
            vf[vdst + 160]     = cvt_tf32(v0.z);
            vf[vdst + 240]     = cvt_tf32(v0.w);
            vf[vdst + 320 + 8] = cvt_tf32(v1.x);
            vf[vdst + 400 + 8] = cvt_tf32(v1.y);
            vf[vdst + 480 + 8] = cvt_tf32(v1.z);
            vf[vdst + 560 + 8] = cvt_tf32(v1.w);
        }
        __syncthreads();
    }

    // ---- finalize: /l, write to g_mid[b, n, h*64 + c] ----
    const float il0 = 1.f / l0, il1 = 1.f / l1;
    const int row0 = qblk + w * 16 + qg;
    const int row1 = row0 + 8;
#pragma unroll
    for (int n = 0; n < 8; ++n) {
        float2 olo = make_float2(O[n][0] * il0, O[n][1] * il0);
        float2 ohi = make_float2(O[n][2] * il1, O[n][3] * il1);
        *(float2*)&g_mid[(size_t)(b * NN + row0) * HIDDEN
                         + h * DH + n * 8 + 2 * q] = olo;
        *(float2*)&g_mid[(size_t)(b * NN + row1) * HIDDEN
                         + h * DH + n * 8 + 2 * q] = ohi;
    }
}

// attn dynamic smem: KF+VF (2*5248 u32) + staging (2*4352 floats) = 76800 B
#define ATTN_SMEM (4 * (4 * 4 * TSTRIDE + 4 * STG_CHUNK))

// =====================================================================
extern "C" void kernel_launch(void* const* d_in, const int* in_sizes, int n_in,
                              void* d_out, int out_size)
{
    const float *x = nullptr, *bias = nullptr, *wqkv = nullptr, *wout = nullptr;
    for (int i = 0; i < n_in; ++i) {
        switch (in_sizes[i]) {
            case 4194304:  x    = (const float*)d_in[i]; break;  // x [4,2048,512]
            case 33554432: bias = (const float*)d_in[i]; break;  // pos_bias [8,2048,2048]
            case 786432:   wqkv = (const float*)d_in[i]; break;  // W_qkv [512,1536]
            case 262144:   wout = (const float*)d_in[i]; break;  // W_out [512,512]
        }
    }

    void *p_qkv = nullptr, *p_mid = nullptr;
    cudaGetSymbolAddress(&p_qkv, g_qkv);
    cudaGetSymbolAddress(&p_mid, g_mid);

    // opt-in to >48KB dynamic smem (non-stream call: capture-safe, idempotent)
    cudaFuncSetAttribute(attn_tf32,
                         cudaFuncAttributeMaxDynamicSharedMemorySize,
                         ATTN_SMEM);

    // 1) qkv = x @ W_qkv
    sgemm128<<<dim3(THC / 64, (BB * NN) / 128), 256>>>(
        x, wqkv, (float*)p_qkv, BB * NN, THC, DIM);

    // 2) split + rotary + scale
    qkv_transform<<<(BB * HEADS * NN * 32) / 256, 256>>>();

    // 3) fused flash attention (tf32 tensor cores, cp.async pipelined)
    attn_tf32<<<dim3(NN / 128, HEADS, BB), 256, ATTN_SMEM>>>(bias);

    // 4) out = mid @ W_out
    sgemm128<<<dim3(DIM / 64, (BB * NN) / 128), 256>>>(
        (const float*)p_mid, wout, (float*)d_out, BB * NN, DIM, HIDDEN);
}